// round 1
// baseline (speedup 1.0000x reference)
#include <cuda_runtime.h>
#include <cub/cub.cuh>

// ---------------- problem constants ----------------
namespace {
constexpr int   F      = 64;
constexpr int   NXc    = 65;
constexpr int   NYc    = 87;
constexpr int   Vc     = NXc * NYc;   // 5655
constexpr int   Bc     = 8;
constexpr int   Sc     = Bc * Vc;     // 45240
constexpr int   NMAX   = 1000000;
constexpr int   EMAX   = 8000000;
constexpr float VOXELf = 4.0f;
}

// ---------------- static device scratch (no allocs allowed) ----------------
__device__ int           g_cluster[NMAX];
__device__ int           g_count[Sc];
__device__ unsigned      g_keys_in[EMAX];
__device__ unsigned      g_keys_out[EMAX];
__device__ unsigned char g_temp[160u * 1024u * 1024u];

// ---------------- helpers ----------------
__device__ __forceinline__ void atomicMaxF(float* addr, float v) {
    // signed-int view for positives, unsigned view for negatives
    if (v >= 0.0f) atomicMax((int*)addr, __float_as_int(v));
    else           atomicMin((unsigned int*)addr, __float_as_uint(v));
}

// ---------------- kernels ----------------

// init: x_pool region -> -inf, pos region -> 0, counts -> 0, batch_out written
__global__ void k_init(float* __restrict__ out) {
    int i = blockIdx.x * blockDim.x + threadIdx.x;
    if (i < Sc * F) ((unsigned*)out)[i] = 0xFF800000u;          // -inf
    if (i < Sc * 3) out[Sc * F + i] = 0.0f;
    if (i < Sc) {
        out[Sc * F + Sc * 3 + i] = (float)(i / Vc);             // batch_out
        g_count[i] = 0;
    }
}

// cluster assignment + pos sums + counts
__global__ void k_cluster(const float* __restrict__ pos,
                          const int* __restrict__ batch,
                          float* __restrict__ pos_out,  // out + Sc*F
                          int N) {
    int i = blockIdx.x * blockDim.x + threadIdx.x;
    if (i >= N) return;
    float px = pos[3 * i + 0];
    float py = pos[3 * i + 1];
    float pt = pos[3 * i + 2];
    int c0 = (int)floorf(px / VOXELf); c0 = min(max(c0, 0), NXc - 1);
    int c1 = (int)floorf(py / VOXELf); c1 = min(max(c1, 0), NYc - 1);
    int cl = batch[i] * Vc + c0 * NYc + c1;
    g_cluster[i] = cl;
    atomicAdd(&pos_out[cl * 3 + 0], px);
    atomicAdd(&pos_out[cl * 3 + 1], py);
    atomicAdd(&pos_out[cl * 3 + 2], pt);
    atomicAdd(&g_count[cl], 1);
}

// x scatter-max: one thread per float4 of a node's row
__global__ void k_xmax(const float4* __restrict__ x4,
                       float* __restrict__ xp,   // out (x_pool region)
                       int N) {
    int i = blockIdx.x * blockDim.x + threadIdx.x;
    int total = N * (F / 4);
    if (i >= total) return;
    int node = i >> 4;             // /16 float4s per row
    int q    = (i & 15) << 2;      // feature offset
    float4 v = x4[i];
    int base = g_cluster[node] * F + q;
    atomicMaxF(xp + base + 0, v.x);
    atomicMaxF(xp + base + 1, v.y);
    atomicMaxF(xp + base + 2, v.z);
    atomicMaxF(xp + base + 3, v.w);
}

// packed edge keys: key = r * Sc + c  (< 2^31)
__global__ void k_edgekey(const int* __restrict__ ei, int E) {
    int i = blockIdx.x * blockDim.x + threadIdx.x;
    if (i >= E) return;
    unsigned r = (unsigned)g_cluster[ei[i]];
    unsigned c = (unsigned)g_cluster[ei[E + i]];
    g_keys_in[i] = r * (unsigned)Sc + c;
}

// emit sorted/deduped edges as float (-1 for dup or self-loop)
__global__ void k_edgeout(float* __restrict__ er, int E) {
    int i = blockIdx.x * blockDim.x + threadIdx.x;
    if (i >= E) return;
    unsigned k    = g_keys_out[i];
    unsigned prev = (i == 0) ? 0xFFFFFFFFu : g_keys_out[i - 1];
    unsigned r = k / (unsigned)Sc;
    unsigned c = k - r * (unsigned)Sc;
    bool valid = (k != prev) && (r != c);
    er[i]     = valid ? (float)r : -1.0f;
    er[E + i] = valid ? (float)c : -1.0f;
}

// finalize: mask empty x_pool rows to 0, divide pos sums by count, write mask
__global__ void k_final(float* __restrict__ out, int E) {
    int i = blockIdx.x * blockDim.x + threadIdx.x;
    if (i < Sc * F) {
        int cl = i >> 6;
        if (g_count[cl] == 0) out[i] = 0.0f;
    }
    if (i < Sc * 3) {
        int cl = i / 3;
        float cnt = (float)g_count[cl];
        out[Sc * F + i] = out[Sc * F + i] / fmaxf(cnt, 1.0f);
    }
    if (i < Sc) {
        // mask lives after edge_out
        out[Sc * F + Sc * 3 + Sc + 2 * E + i] = (g_count[i] > 0) ? 1.0f : 0.0f;
    }
}

// ---------------- launch ----------------
extern "C" void kernel_launch(void* const* d_in, const int* in_sizes, int n_in,
                              void* d_out, int out_size) {
    const float* x     = (const float*)d_in[0];
    const float* pos   = (const float*)d_in[1];
    const int*   batch = (const int*)d_in[2];
    const int*   ei    = (const int*)d_in[3];
    float* out = (float*)d_out;

    int N = in_sizes[2];
    int E = in_sizes[3] / 2;

    void *p_kin, *p_kout, *p_temp;
    cudaGetSymbolAddress(&p_kin,  g_keys_in);
    cudaGetSymbolAddress(&p_kout, g_keys_out);
    cudaGetSymbolAddress(&p_temp, g_temp);

    constexpr int T = 256;

    k_init<<<(Sc * F + T - 1) / T, T>>>(out);
    k_cluster<<<(N + T - 1) / T, T>>>(pos, batch, out + Sc * F, N);
    k_xmax<<<(N * (F / 4) + T - 1) / T, T>>>((const float4*)x, out, N);
    k_edgekey<<<(E + T - 1) / T, T>>>(ei, E);

    size_t temp_bytes = 0;
    cub::DeviceRadixSort::SortKeys(nullptr, temp_bytes,
                                   (const unsigned*)p_kin, (unsigned*)p_kout,
                                   E, 0, 31);
    if (temp_bytes > sizeof(g_temp)) temp_bytes = sizeof(g_temp);  // safety clamp
    cub::DeviceRadixSort::SortKeys(p_temp, temp_bytes,
                                   (const unsigned*)p_kin, (unsigned*)p_kout,
                                   E, 0, 31);

    k_edgeout<<<(E + T - 1) / T, T>>>(out + Sc * F + Sc * 3 + Sc, E);
    k_final<<<(Sc * F + T - 1) / T, T>>>(out, E);
}

// round 5
// speedup vs baseline: 1.1933x; 1.1933x over previous
#include <cuda_runtime.h>
#include <cub/cub.cuh>

// ---------------- problem constants ----------------
namespace {
constexpr int   F      = 64;
constexpr int   NXc    = 65;
constexpr int   NYc    = 87;
constexpr int   Vc     = NXc * NYc;   // 5655
constexpr int   Bc     = 8;
constexpr int   Sc     = Bc * Vc;     // 45240  (< 2^16)
constexpr int   NMAX   = 1000000;
constexpr int   EMAX   = 8000000;
constexpr float VOXELf = 4.0f;
}

// ---------------- static device scratch (no allocs allowed) ----------------
__device__ unsigned short g_cluster16[NMAX];
__device__ int            g_count[Sc];
__device__ unsigned       g_keys_in[EMAX];
__device__ unsigned       g_keys_out[EMAX];
__device__ unsigned char  g_temp[160u * 1024u * 1024u];

// ---------------- host-side streams/events (host objects only) ----------
struct StreamPack {
    cudaStream_t s2 = nullptr;
    cudaEvent_t  ev_fork = nullptr, ev_join = nullptr;
    StreamPack() {
        cudaStreamCreateWithFlags(&s2, cudaStreamNonBlocking);
        cudaEventCreateWithFlags(&ev_fork, cudaEventDisableTiming);
        cudaEventCreateWithFlags(&ev_join, cudaEventDisableTiming);
    }
};
static StreamPack g_sp;

// ---------------- order-preserving f32 <-> u32 ----------------
__device__ __forceinline__ unsigned f2ord(float f) {
    unsigned u = __float_as_uint(f);
    unsigned m = (unsigned)((int)u >> 31);        // all-ones if negative
    return u ^ (m | 0x80000000u);
}
__device__ __forceinline__ float ord2f(unsigned u) {
    unsigned bits = (u & 0x80000000u) ? (u ^ 0x80000000u) : ~u;
    return __uint_as_float(bits);
}

// ---------------- kernels ----------------

// init: x_pool region -> 0 (ord sentinel), pos -> 0, counts -> 0, batch_out
__global__ void k_init(float* __restrict__ out) {
    int i = blockIdx.x * blockDim.x + threadIdx.x;
    if (i < Sc * F) ((unsigned*)out)[i] = 0u;                   // ord sentinel
    if (i < Sc * 3) out[Sc * F + i] = 0.0f;
    if (i < Sc) {
        out[Sc * F + Sc * 3 + i] = (float)(i / Vc);             // batch_out
        g_count[i] = 0;
    }
}

// cluster assignment + pos sums + counts
__global__ void k_cluster(const float* __restrict__ pos,
                          const int* __restrict__ batch,
                          float* __restrict__ pos_out,  // out + Sc*F
                          int N) {
    int i = blockIdx.x * blockDim.x + threadIdx.x;
    if (i >= N) return;
    float px = pos[3 * i + 0];
    float py = pos[3 * i + 1];
    float pt = pos[3 * i + 2];
    int c0 = (int)floorf(px / VOXELf); c0 = min(max(c0, 0), NXc - 1);
    int c1 = (int)floorf(py / VOXELf); c1 = min(max(c1, 0), NYc - 1);
    int cl = batch[i] * Vc + c0 * NYc + c1;
    g_cluster16[i] = (unsigned short)cl;
    atomicAdd(&pos_out[cl * 3 + 0], px);
    atomicAdd(&pos_out[cl * 3 + 1], py);
    atomicAdd(&pos_out[cl * 3 + 2], pt);
    atomicAdd(&g_count[cl], 1);
}

// x scatter-max: one thread per float4; u32 RED.MAX on ord-encoded values
__global__ void k_xmax(const float4* __restrict__ x4,
                       unsigned* __restrict__ xp,   // x_pool region (as u32)
                       int N) {
    int i = blockIdx.x * blockDim.x + threadIdx.x;
    int total = N * (F / 4);
    if (i >= total) return;
    int node = i >> 4;             // 16 float4s per row
    int q    = (i & 15) << 2;      // feature offset
    float4 v = x4[i];
    unsigned* addr = xp + (int)g_cluster16[node] * F + q;
    atomicMax(addr + 0, f2ord(v.x));   // RED.MAX.U32 (no return)
    atomicMax(addr + 1, f2ord(v.y));
    atomicMax(addr + 2, f2ord(v.z));
    atomicMax(addr + 3, f2ord(v.w));
}

// packed edge keys: key = (r<<16) | c — u32 order == lexsort(r,c)
__global__ void k_edgekey(const int* __restrict__ ei, int E) {
    int i = blockIdx.x * blockDim.x + threadIdx.x;
    int E4 = E >> 2;
    if (i < E4) {
        int4 a = ((const int4*)ei)[i];
        int4 b = ((const int4*)(ei + E))[i];
        uint4 k;
        k.x = ((unsigned)g_cluster16[a.x] << 16) | g_cluster16[b.x];
        k.y = ((unsigned)g_cluster16[a.y] << 16) | g_cluster16[b.y];
        k.z = ((unsigned)g_cluster16[a.z] << 16) | g_cluster16[b.z];
        k.w = ((unsigned)g_cluster16[a.w] << 16) | g_cluster16[b.w];
        ((uint4*)g_keys_in)[i] = k;
    }
    int t = E4 * 4 + i;
    if (i < (E & 3) && t < E) {
        g_keys_in[t] = ((unsigned)g_cluster16[ei[t]] << 16)
                     | g_cluster16[ei[E + t]];
    }
}

// emit sorted/deduped edges as float (-1 for dup or self-loop)
__global__ void k_edgeout(float* __restrict__ er, int E) {
    int i = blockIdx.x * blockDim.x + threadIdx.x;
    if (i >= E) return;
    unsigned k    = g_keys_out[i];
    unsigned prev = (i == 0) ? 0xFFFFFFFFu : g_keys_out[i - 1];
    unsigned r = k >> 16;
    unsigned c = k & 0xFFFFu;
    bool valid = (k != prev) && (r != c);
    er[i]     = valid ? (float)r : -1.0f;
    er[E + i] = valid ? (float)c : -1.0f;
}

// finalize: decode ord->float (0 for empty), divide pos sums, write mask
__global__ void k_final(float* __restrict__ out, int E) {
    int i = blockIdx.x * blockDim.x + threadIdx.x;
    if (i < Sc * F) {
        int cl = i >> 6;
        unsigned u = ((unsigned*)out)[i];
        out[i] = (g_count[cl] == 0) ? 0.0f : ord2f(u);
    }
    if (i < Sc * 3) {
        int cl = i / 3;
        float cnt = (float)g_count[cl];
        out[Sc * F + i] = out[Sc * F + i] / fmaxf(cnt, 1.0f);
    }
    if (i < Sc) {
        out[Sc * F + Sc * 3 + Sc + 2 * E + i] = (g_count[i] > 0) ? 1.0f : 0.0f;
    }
}

// ---------------- launch ----------------
extern "C" void kernel_launch(void* const* d_in, const int* in_sizes, int n_in,
                              void* d_out, int out_size) {
    const float* x     = (const float*)d_in[0];
    const float* pos   = (const float*)d_in[1];
    const int*   batch = (const int*)d_in[2];
    const int*   ei    = (const int*)d_in[3];
    float* out = (float*)d_out;

    int N = in_sizes[2];
    int E = in_sizes[3] / 2;

    void *p_kin, *p_kout, *p_temp;
    cudaGetSymbolAddress(&p_kin,  g_keys_in);
    cudaGetSymbolAddress(&p_kout, g_keys_out);
    cudaGetSymbolAddress(&p_temp, g_temp);

    constexpr int T = 256;
    cudaStream_t s0 = 0;            // captured origin stream
    cudaStream_t s2 = g_sp.s2;

    // main stream: init + cluster (both paths depend on these)
    k_init<<<(Sc * F + T - 1) / T, T, 0, s0>>>(out);
    k_cluster<<<(N + T - 1) / T, T, 0, s0>>>(pos, batch, out + Sc * F, N);

    // fork: edge path on s2
    cudaEventRecord(g_sp.ev_fork, s0);
    cudaStreamWaitEvent(s2, g_sp.ev_fork, 0);

    k_edgekey<<<((E >> 2) + T - 1) / T, T, 0, s2>>>(ei, E);
    size_t temp_bytes = 0;
    cub::DeviceRadixSort::SortKeys(nullptr, temp_bytes,
                                   (const unsigned*)p_kin, (unsigned*)p_kout,
                                   E, 0, 32, s2);
    if (temp_bytes > sizeof(g_temp)) temp_bytes = sizeof(g_temp);
    cub::DeviceRadixSort::SortKeys(p_temp, temp_bytes,
                                   (const unsigned*)p_kin, (unsigned*)p_kout,
                                   E, 0, 32, s2);
    k_edgeout<<<(E + T - 1) / T, T, 0, s2>>>(out + Sc * F + Sc * 3 + Sc, E);
    cudaEventRecord(g_sp.ev_join, s2);

    // x path stays on main stream, overlapped with the sort
    k_xmax<<<(N * (F / 4) + T - 1) / T, T, 0, s0>>>((const float4*)x,
                                                    (unsigned*)out, N);
    k_final<<<(Sc * F + T - 1) / T, T, 0, s0>>>(out, E);

    // join
    cudaStreamWaitEvent(s0, g_sp.ev_join, 0);
}